// round 1
// baseline (speedup 1.0000x reference)
#include <cuda_runtime.h>
#include <math.h>

#define B_ 4
#define N_ 4096
#define C_ 256
#define D_ 64

// Scratch (allocation-free contract: __device__ globals)
__device__ float g_f[B_ * N_ * D_];      // 4 MB
__device__ float g_g[B_ * N_ * D_];      // 4 MB
__device__ float g_h[B_ * N_ * C_];      // 16 MB (only touched if gamma != 0)
__device__ float g_rowsum[B_ * N_];      // 64 KB

// ---------------------------------------------------------------------------
// Zero the rowsum accumulator (graph is replayed many times; must re-zero).
// ---------------------------------------------------------------------------
__global__ void zero_rowsum_kernel() {
    int i = blockIdx.x * blockDim.x + threadIdx.x;
    if (i < B_ * N_) g_rowsum[i] = 0.0f;
}

// ---------------------------------------------------------------------------
// f = x @ Wf, g = x @ Wg   (per-pixel channel projections, K=256, Nout=64)
// Block: 32 rows of one batch. Thread (r = tid/8, dg = tid%8) computes
// 8 f-outputs and 8 g-outputs for row r.
// ---------------------------------------------------------------------------
__global__ void __launch_bounds__(256) fg_kernel(const float* __restrict__ x,
                                                 const float* __restrict__ Wf,
                                                 const float* __restrict__ Wg) {
    __shared__ float xs[C_][32];       // x tile, transposed: xs[c][r]  (32 KB)
    __shared__ float ws[2][16][D_];    // Wf / Wg chunk of 16 c-rows     (8 KB)

    const int b    = blockIdx.y;
    const int row0 = blockIdx.x * 32;
    const int r    = threadIdx.x >> 3;   // 0..31
    const int dg   = threadIdx.x & 7;    // 0..7

    // Load 32 x-rows into smem (transposed so compute reads are conflict-free)
    {
        const float4* src = reinterpret_cast<const float4*>(
            x + ((size_t)b * N_ + row0 + r) * C_ + dg * 32);
#pragma unroll
        for (int i = 0; i < 8; i++) {
            float4 v = src[i];
            int c = dg * 32 + i * 4;
            xs[c + 0][r] = v.x; xs[c + 1][r] = v.y;
            xs[c + 2][r] = v.z; xs[c + 3][r] = v.w;
        }
    }

    float accf[8] = {}, accg[8] = {};
    for (int c0 = 0; c0 < C_; c0 += 16) {
        __syncthreads();   // xs ready (iter 0) / previous W chunk consumed
        {
            const float4* wf4 = reinterpret_cast<const float4*>(Wf + c0 * D_);
            const float4* wg4 = reinterpret_cast<const float4*>(Wg + c0 * D_);
            reinterpret_cast<float4*>(&ws[0][0][0])[threadIdx.x] = wf4[threadIdx.x];
            reinterpret_cast<float4*>(&ws[1][0][0])[threadIdx.x] = wg4[threadIdx.x];
        }
        __syncthreads();
#pragma unroll
        for (int cc = 0; cc < 16; cc++) {
            float xv = xs[c0 + cc][r];
#pragma unroll
            for (int j = 0; j < 8; j++) {
                accf[j] = fmaf(xv, ws[0][cc][dg * 8 + j], accf[j]);
                accg[j] = fmaf(xv, ws[1][cc][dg * 8 + j], accg[j]);
            }
        }
    }

    size_t off = ((size_t)b * N_ + row0 + r) * D_ + dg * 8;
    float4* fo = reinterpret_cast<float4*>(g_f + off);
    float4* go = reinterpret_cast<float4*>(g_g + off);
    fo[0] = make_float4(accf[0], accf[1], accf[2], accf[3]);
    fo[1] = make_float4(accf[4], accf[5], accf[6], accf[7]);
    go[0] = make_float4(accg[0], accg[1], accg[2], accg[3]);
    go[1] = make_float4(accg[4], accg[5], accg[6], accg[7]);
}

// ---------------------------------------------------------------------------
// s tile = g @ f^T (128x128, K=64), then e = exp(s) written to beta
// (unnormalized) and per-row partial sums atomically accumulated.
// No max-subtraction: |s| < ~50 << 88 so fp32 exp cannot overflow.
// ---------------------------------------------------------------------------
__global__ void __launch_bounds__(256) attn_kernel(float* __restrict__ beta) {
    __shared__ float gs[32][132];   // [k][row], padded
    __shared__ float fs[32][132];   // [k][col], padded

    const int b    = blockIdx.z;
    const int row0 = blockIdx.y * 128;
    const int col0 = blockIdx.x * 128;
    const int tx   = threadIdx.x & 15;   // col group
    const int ty   = threadIdx.x >> 4;   // row group

    const int rl = threadIdx.x >> 1;         // loader row 0..127
    const int kh = (threadIdx.x & 1) * 4;    // loader float4 base 0 or 4

    float acc[8][8] = {};

    for (int k0 = 0; k0 < D_; k0 += 32) {
        __syncthreads();
        {
            const float4* gsrc = reinterpret_cast<const float4*>(
                g_g + ((size_t)b * N_ + row0 + rl) * D_ + k0);
            const float4* fsrc = reinterpret_cast<const float4*>(
                g_f + ((size_t)b * N_ + col0 + rl) * D_ + k0);
#pragma unroll
            for (int p = 0; p < 4; p++) {
                float4 v = gsrc[kh + p];
                float4 w = fsrc[kh + p];
                int kk = (kh + p) * 4;
                gs[kk + 0][rl] = v.x; gs[kk + 1][rl] = v.y;
                gs[kk + 2][rl] = v.z; gs[kk + 3][rl] = v.w;
                fs[kk + 0][rl] = w.x; fs[kk + 1][rl] = w.y;
                fs[kk + 2][rl] = w.z; fs[kk + 3][rl] = w.w;
            }
        }
        __syncthreads();
#pragma unroll
        for (int k = 0; k < 32; k++) {
            float a[8], bb[8];
            *reinterpret_cast<float4*>(&a[0])  = *reinterpret_cast<const float4*>(&gs[k][ty * 8]);
            *reinterpret_cast<float4*>(&a[4])  = *reinterpret_cast<const float4*>(&gs[k][ty * 8 + 4]);
            *reinterpret_cast<float4*>(&bb[0]) = *reinterpret_cast<const float4*>(&fs[k][tx * 8]);
            *reinterpret_cast<float4*>(&bb[4]) = *reinterpret_cast<const float4*>(&fs[k][tx * 8 + 4]);
#pragma unroll
            for (int i = 0; i < 8; i++)
#pragma unroll
                for (int j = 0; j < 8; j++)
                    acc[i][j] = fmaf(a[i], bb[j], acc[i][j]);
        }
    }

    // exp, store, and row-sum reduce (16 lanes per row share a half-warp)
#pragma unroll
    for (int i = 0; i < 8; i++) {
        float e[8];
        float rsum = 0.0f;
#pragma unroll
        for (int j = 0; j < 8; j++) {
            e[j] = __expf(acc[i][j]);
            rsum += e[j];
        }
        size_t rowg = (size_t)b * N_ + row0 + ty * 8 + i;
        float4* dst = reinterpret_cast<float4*>(beta + rowg * (size_t)N_ + col0 + tx * 8);
        dst[0] = make_float4(e[0], e[1], e[2], e[3]);
        dst[1] = make_float4(e[4], e[5], e[6], e[7]);

        rsum += __shfl_xor_sync(0xffffffffu, rsum, 8, 16);
        rsum += __shfl_xor_sync(0xffffffffu, rsum, 4, 16);
        rsum += __shfl_xor_sync(0xffffffffu, rsum, 2, 16);
        rsum += __shfl_xor_sync(0xffffffffu, rsum, 1, 16);
        if (tx == 0) atomicAdd(&g_rowsum[rowg], rsum);
    }
}

// ---------------------------------------------------------------------------
// beta[row, :] /= rowsum[row]
// ---------------------------------------------------------------------------
__global__ void __launch_bounds__(256) norm_kernel(float* __restrict__ beta) {
    const size_t row = blockIdx.x;
    const float inv = 1.0f / g_rowsum[row];
    float4* p = reinterpret_cast<float4*>(beta + row * (size_t)N_);
    for (int i = threadIdx.x; i < N_ / 4; i += 256) {
        float4 v = p[i];
        v.x *= inv; v.y *= inv; v.z *= inv; v.w *= inv;
        p[i] = v;
    }
}

// ---------------------------------------------------------------------------
// Generic-path h = x @ Wh (only runs when gamma != 0; early-exits otherwise)
// ---------------------------------------------------------------------------
__global__ void h_kernel(const float* __restrict__ x, const float* __restrict__ Wh,
                         const float* __restrict__ gamma) {
    if (gamma[0] == 0.0f) return;
    const int b = blockIdx.y;
    const int n = blockIdx.x;
    const int c = threadIdx.x;
    const float* xr = x + ((size_t)b * N_ + n) * C_;
    float acc = 0.0f;
    for (int k = 0; k < C_; k++) acc = fmaf(xr[k], Wh[k * C_ + c], acc);
    g_h[((size_t)b * N_ + n) * C_ + c] = acc;
}

// ---------------------------------------------------------------------------
// out = gamma * (beta @ h) + x.  With gamma == 0 this is a pure copy.
// ---------------------------------------------------------------------------
__global__ void out_kernel(const float* __restrict__ x, const float* __restrict__ gamma,
                           float* __restrict__ out, const float* __restrict__ beta) {
    const int b = blockIdx.y;
    const int n = blockIdx.x;
    const int c = threadIdx.x;
    const size_t idx = ((size_t)b * N_ + n) * C_ + c;
    const float gm = gamma[0];
    if (gm == 0.0f) { out[idx] = x[idx]; return; }
    const float* brow = beta + ((size_t)b * N_ + n) * (size_t)N_;
    float acc = 0.0f;
    for (int m = 0; m < N_; m++)
        acc = fmaf(brow[m], g_h[((size_t)b * N_ + m) * C_ + c], acc);
    out[idx] = fmaf(gm, acc, x[idx]);
}

// ---------------------------------------------------------------------------
extern "C" void kernel_launch(void* const* d_in, const int* in_sizes, int n_in,
                              void* d_out, int out_size) {
    const float* x     = (const float*)d_in[0];
    const float* Wf    = (const float*)d_in[1];
    const float* Wg    = (const float*)d_in[2];
    const float* Wh    = (const float*)d_in[3];
    const float* gamma = (const float*)d_in[4];

    float* out  = (float*)d_out;
    float* beta = out + (size_t)B_ * N_ * C_;   // out first, then beta (tuple order)

    zero_rowsum_kernel<<<(B_ * N_) / 256, 256>>>();
    fg_kernel<<<dim3(N_ / 32, B_), 256>>>(x, Wf, Wg);
    h_kernel<<<dim3(N_, B_), 256>>>(x, Wh, gamma);                 // no-op when gamma==0
    attn_kernel<<<dim3(N_ / 128, N_ / 128, B_), 256>>>(beta);
    norm_kernel<<<B_ * N_, 256>>>(beta);
    out_kernel<<<dim3(N_, B_), 256>>>(x, gamma, out, beta);
}

// round 3
// speedup vs baseline: 1.2513x; 1.2513x over previous
#include <cuda_runtime.h>
#include <cuda_bf16.h>
#include <stdint.h>
#include <math.h>

#define B_ 4
#define N_ 4096
#define C_ 256
#define D_ 64

// ---- scratch (allocation-free contract) -----------------------------------
__device__ uint16_t g_ghi[B_ * N_ * D_];   // bf16 hi of g
__device__ uint16_t g_glo[B_ * N_ * D_];   // bf16 lo of g
__device__ uint16_t g_fhi[B_ * N_ * D_];   // bf16 hi of f
__device__ uint16_t g_flo[B_ * N_ * D_];   // bf16 lo of f
__device__ float    g_h[B_ * N_ * C_];     // only touched if gamma != 0
__device__ float    g_rowsum[B_ * N_];

__device__ __forceinline__ uint32_t smem_u32(const void* p) {
    uint32_t a;
    asm("{ .reg .u64 t; cvta.to.shared.u64 t, %1; cvt.u32.u64 %0, t; }" : "=r"(a) : "l"(p));
    return a;
}

// ---------------------------------------------------------------------------
__global__ void zero_rowsum_kernel() {
    int i = blockIdx.x * blockDim.x + threadIdx.x;
    if (i < B_ * N_) g_rowsum[i] = 0.0f;
}

// ---------------------------------------------------------------------------
// f = x@Wf, g = x@Wg, emitted as bf16 hi/lo split.
// ---------------------------------------------------------------------------
__global__ void __launch_bounds__(256) fg_kernel(const float* __restrict__ x,
                                                 const float* __restrict__ Wf,
                                                 const float* __restrict__ Wg) {
    __shared__ float xs[C_][32];
    __shared__ float ws[2][16][D_];

    const int b    = blockIdx.y;
    const int row0 = blockIdx.x * 32;
    const int r    = threadIdx.x >> 3;
    const int dg   = threadIdx.x & 7;

    {
        const float4* src = reinterpret_cast<const float4*>(
            x + ((size_t)b * N_ + row0 + r) * C_ + dg * 32);
#pragma unroll
        for (int i = 0; i < 8; i++) {
            float4 v = src[i];
            int c = dg * 32 + i * 4;
            xs[c + 0][r] = v.x; xs[c + 1][r] = v.y;
            xs[c + 2][r] = v.z; xs[c + 3][r] = v.w;
        }
    }

    float accf[8] = {}, accg[8] = {};
    for (int c0 = 0; c0 < C_; c0 += 16) {
        __syncthreads();
        {
            const float4* wf4 = reinterpret_cast<const float4*>(Wf + c0 * D_);
            const float4* wg4 = reinterpret_cast<const float4*>(Wg + c0 * D_);
            reinterpret_cast<float4*>(&ws[0][0][0])[threadIdx.x] = wf4[threadIdx.x];
            reinterpret_cast<float4*>(&ws[1][0][0])[threadIdx.x] = wg4[threadIdx.x];
        }
        __syncthreads();
#pragma unroll
        for (int cc = 0; cc < 16; cc++) {
            float xv = xs[c0 + cc][r];
#pragma unroll
            for (int j = 0; j < 8; j++) {
                accf[j] = fmaf(xv, ws[0][cc][dg * 8 + j], accf[j]);
                accg[j] = fmaf(xv, ws[1][cc][dg * 8 + j], accg[j]);
            }
        }
    }

    uint4 fh, fl, gh, gl;
    uint16_t* fhp = (uint16_t*)&fh; uint16_t* flp = (uint16_t*)&fl;
    uint16_t* ghp = (uint16_t*)&gh; uint16_t* glp = (uint16_t*)&gl;
#pragma unroll
    for (int j = 0; j < 8; j++) {
        __nv_bfloat16 h1 = __float2bfloat16_rn(accf[j]);
        __nv_bfloat16 l1 = __float2bfloat16_rn(accf[j] - __bfloat162float(h1));
        __nv_bfloat16 h2 = __float2bfloat16_rn(accg[j]);
        __nv_bfloat16 l2 = __float2bfloat16_rn(accg[j] - __bfloat162float(h2));
        fhp[j] = *(uint16_t*)&h1; flp[j] = *(uint16_t*)&l1;
        ghp[j] = *(uint16_t*)&h2; glp[j] = *(uint16_t*)&l2;
    }
    size_t off = ((size_t)b * N_ + row0 + r) * D_ + dg * 8;
    *reinterpret_cast<uint4*>(g_fhi + off) = fh;
    *reinterpret_cast<uint4*>(g_flo + off) = fl;
    *reinterpret_cast<uint4*>(g_ghi + off) = gh;
    *reinterpret_cast<uint4*>(g_glo + off) = gl;
}

// ---------------------------------------------------------------------------
// Tensor-core (mma.sync bf16) attention: s tile = g@f^T, e=exp(s) written
// unnormalized, rowsums accumulated. bf16-split: hi*hi + hi*lo + lo*hi.
// CTA tile 128x128, 8 warps (4 m x 2 n), warp tile 32x64.
// ---------------------------------------------------------------------------
#define PADE 72   // bf16 elements per smem row (64 + 8 pad => 144B stride)
#define TILE_BYTES (128 * PADE * 2)

__global__ void __launch_bounds__(256, 2) attn_mma_kernel(float* __restrict__ beta) {
    extern __shared__ __align__(16) char smem[];
    __shared__ float srow[128];

    char* sAhi = smem;
    char* sAlo = smem + TILE_BYTES;
    char* sBhi = smem + 2 * TILE_BYTES;
    char* sBlo = smem + 3 * TILE_BYTES;

    const int b    = blockIdx.z;
    const int row0 = blockIdx.y * 128;
    const int col0 = blockIdx.x * 128;
    const int tid  = threadIdx.x;
    const int wid  = tid >> 5;
    const int lane = tid & 31;

    // ---- load g (A) and f (B) tiles, hi & lo, padded rows ----
    for (int i = tid; i < 1024; i += 256) {
        int r = i >> 3, c = i & 7;
        int so = r * (PADE * 2) + c * 16;
        size_t ga = ((size_t)b * N_ + row0 + r) * D_ + c * 8;
        size_t gb = ((size_t)b * N_ + col0 + r) * D_ + c * 8;
        *reinterpret_cast<uint4*>(sAhi + so) = *reinterpret_cast<const uint4*>(g_ghi + ga);
        *reinterpret_cast<uint4*>(sAlo + so) = *reinterpret_cast<const uint4*>(g_glo + ga);
        *reinterpret_cast<uint4*>(sBhi + so) = *reinterpret_cast<const uint4*>(g_fhi + gb);
        *reinterpret_cast<uint4*>(sBlo + so) = *reinterpret_cast<const uint4*>(g_flo + gb);
    }
    if (tid < 128) srow[tid] = 0.0f;
    __syncthreads();

    const int wm = wid & 3;        // m block (32 rows)
    const int wn = wid >> 2;       // n block (64 cols)

    float d[2][8][4];
#pragma unroll
    for (int mi = 0; mi < 2; mi++)
#pragma unroll
        for (int ni = 0; ni < 8; ni++)
#pragma unroll
            for (int q = 0; q < 4; q++) d[mi][ni][q] = 0.0f;

    const uint32_t aRow = (uint32_t)(wm * 32 + (lane & 15));
    const uint32_t aK8  = (uint32_t)((lane >> 4) * 8);
    const uint32_t bRow = (uint32_t)(wn * 64 + (lane & 7));
    const uint32_t bK8  = (uint32_t)(((lane >> 3) & 1) * 8);

#pragma unroll
    for (int term = 0; term < 3; term++) {
        const uint32_t Abase = smem_u32(term == 2 ? sAlo : sAhi);
        const uint32_t Bbase = smem_u32(term == 1 ? sBlo : sBhi);
#pragma unroll
        for (int k0 = 0; k0 < 64; k0 += 16) {
            uint32_t a[2][4];
#pragma unroll
            for (int mi = 0; mi < 2; mi++) {
                uint32_t addr = Abase + (aRow + mi * 16) * (PADE * 2) + (k0 + aK8) * 2;
                asm volatile("ldmatrix.sync.aligned.m8n8.x4.shared.b16 {%0,%1,%2,%3}, [%4];"
                             : "=r"(a[mi][0]), "=r"(a[mi][1]), "=r"(a[mi][2]), "=r"(a[mi][3])
                             : "r"(addr));
            }
#pragma unroll
            for (int ni = 0; ni < 8; ni++) {
                uint32_t bb[2];
                uint32_t addr = Bbase + (bRow + ni * 8) * (PADE * 2) + (k0 + bK8) * 2;
                asm volatile("ldmatrix.sync.aligned.m8n8.x2.shared.b16 {%0,%1}, [%2];"
                             : "=r"(bb[0]), "=r"(bb[1]) : "r"(addr));
#pragma unroll
                for (int mi = 0; mi < 2; mi++) {
                    asm volatile(
                        "mma.sync.aligned.m16n8k16.row.col.f32.bf16.bf16.f32 "
                        "{%0,%1,%2,%3}, {%4,%5,%6,%7}, {%8,%9}, {%0,%1,%2,%3};"
                        : "+f"(d[mi][ni][0]), "+f"(d[mi][ni][1]),
                          "+f"(d[mi][ni][2]), "+f"(d[mi][ni][3])
                        : "r"(a[mi][0]), "r"(a[mi][1]), "r"(a[mi][2]), "r"(a[mi][3]),
                          "r"(bb[0]), "r"(bb[1]));
                }
            }
        }
    }

    // ---- epilogue: exp, store float2, rowsum reduce ----
    const int gRow = lane >> 2;            // 0..7
    const int cPair = (lane & 3) * 2;      // col pair within atom
#pragma unroll
    for (int mi = 0; mi < 2; mi++) {
        const int rl0 = wm * 32 + mi * 16 + gRow;
        const size_t r0 = (size_t)b * N_ + row0 + rl0;
        const size_t r1 = r0 + 8;
        float s0 = 0.0f, s1 = 0.0f;
#pragma unroll
        for (int ni = 0; ni < 8; ni++) {
            float e0 = __expf(d[mi][ni][0]);
            float e1 = __expf(d[mi][ni][1]);
            float e2 = __expf(d[mi][ni][2]);
            float e3 = __expf(d[mi][ni][3]);
            const int col = col0 + wn * 64 + ni * 8 + cPair;
            *reinterpret_cast<float2*>(beta + r0 * (size_t)N_ + col) = make_float2(e0, e1);
            *reinterpret_cast<float2*>(beta + r1 * (size_t)N_ + col) = make_float2(e2, e3);
            s0 += e0 + e1;
            s1 += e2 + e3;
        }
        s0 += __shfl_xor_sync(0xffffffffu, s0, 1);
        s0 += __shfl_xor_sync(0xffffffffu, s0, 2);
        s1 += __shfl_xor_sync(0xffffffffu, s1, 1);
        s1 += __shfl_xor_sync(0xffffffffu, s1, 2);
        if ((lane & 3) == 0) {
            atomicAdd(&srow[rl0], s0);
            atomicAdd(&srow[rl0 + 8], s1);
        }
    }
    __syncthreads();
    if (tid < 128) atomicAdd(&g_rowsum[(size_t)b * N_ + row0 + tid], srow[tid]);
}

// ---------------------------------------------------------------------------
// beta[row, :] /= rowsum[row]
// ---------------------------------------------------------------------------
__global__ void __launch_bounds__(256) norm_kernel(float* __restrict__ beta) {
    const size_t row = blockIdx.x;
    const float inv = 1.0f / g_rowsum[row];
    float4* p = reinterpret_cast<float4*>(beta + row * (size_t)N_);
#pragma unroll
    for (int i = 0; i < 4; i++) {
        int idx = i * 256 + threadIdx.x;
        float4 v = p[idx];
        v.x *= inv; v.y *= inv; v.z *= inv; v.w *= inv;
        p[idx] = v;
    }
}

// ---------------------------------------------------------------------------
__global__ void h_kernel(const float* __restrict__ x, const float* __restrict__ Wh,
                         const float* __restrict__ gamma) {
    if (gamma[0] == 0.0f) return;
    const int b = blockIdx.y;
    const int n = blockIdx.x;
    const int c = threadIdx.x;
    const float* xr = x + ((size_t)b * N_ + n) * C_;
    float acc = 0.0f;
    for (int k = 0; k < C_; k++) acc = fmaf(xr[k], Wh[k * C_ + c], acc);
    g_h[((size_t)b * N_ + n) * C_ + c] = acc;
}

__global__ void out_kernel(const float* __restrict__ x, const float* __restrict__ gamma,
                           float* __restrict__ out, const float* __restrict__ beta) {
    const int b = blockIdx.y;
    const int n = blockIdx.x;
    const int c = threadIdx.x;
    const size_t idx = ((size_t)b * N_ + n) * C_ + c;
    const float gm = gamma[0];
    if (gm == 0.0f) { out[idx] = x[idx]; return; }
    const float* brow = beta + ((size_t)b * N_ + n) * (size_t)N_;
    float acc = 0.0f;
    for (int m = 0; m < N_; m++)
        acc = fmaf(brow[m], g_h[((size_t)b * N_ + m) * C_ + c], acc);
    out[idx] = fmaf(gm, acc, x[idx]);
}

// ---------------------------------------------------------------------------
extern "C" void kernel_launch(void* const* d_in, const int* in_sizes, int n_in,
                              void* d_out, int out_size) {
    const float* x     = (const float*)d_in[0];
    const float* Wf    = (const float*)d_in[1];
    const float* Wg    = (const float*)d_in[2];
    const float* Wh    = (const float*)d_in[3];
    const float* gamma = (const float*)d_in[4];

    float* out  = (float*)d_out;
    float* beta = out + (size_t)B_ * N_ * C_;

    cudaFuncSetAttribute(attn_mma_kernel, cudaFuncAttributeMaxDynamicSharedMemorySize,
                         4 * TILE_BYTES);

    zero_rowsum_kernel<<<(B_ * N_) / 256, 256>>>();
    fg_kernel<<<dim3(N_ / 32, B_), 256>>>(x, Wf, Wg);
    h_kernel<<<dim3(N_, B_), 256>>>(x, Wh, gamma);
    attn_mma_kernel<<<dim3(N_ / 128, N_ / 128, B_), 256, 4 * TILE_BYTES>>>(beta);
    norm_kernel<<<B_ * N_, 256>>>(beta);
    out_kernel<<<dim3(N_, B_), 256>>>(x, gamma, out, beta);
}

// round 4
// speedup vs baseline: 1.3166x; 1.0522x over previous
#include <cuda_runtime.h>
#include <cuda_bf16.h>
#include <stdint.h>
#include <math.h>

#define B_ 4
#define N_ 4096
#define C_ 256
#define D_ 64

// ---- scratch (allocation-free contract) -----------------------------------
__device__ uint16_t g_ghi[B_ * N_ * D_];
__device__ uint16_t g_glo[B_ * N_ * D_];
__device__ uint16_t g_fhi[B_ * N_ * D_];
__device__ uint16_t g_flo[B_ * N_ * D_];
__device__ float    g_h[B_ * N_ * C_];     // only touched if gamma != 0

__device__ __forceinline__ uint32_t smem_u32(const void* p) {
    uint32_t a;
    asm("{ .reg .u64 t; cvta.to.shared.u64 t, %1; cvt.u32.u64 %0, t; }" : "=r"(a) : "l"(p));
    return a;
}
__device__ __forceinline__ void cp16(uint32_t dst, const void* src) {
    asm volatile("cp.async.cg.shared.global [%0], [%1], 16;" :: "r"(dst), "l"(src));
}
#define CP_COMMIT() asm volatile("cp.async.commit_group;" ::: "memory")
#define CP_WAIT0()  asm volatile("cp.async.wait_group 0;" ::: "memory")

#define LDSM4(r, addr) \
    asm volatile("ldmatrix.sync.aligned.m8n8.x4.shared.b16 {%0,%1,%2,%3}, [%4];" \
        : "=r"((r)[0]), "=r"((r)[1]), "=r"((r)[2]), "=r"((r)[3]) : "r"(addr))

#define MMA(dd, A, b0, b1) \
    asm volatile("mma.sync.aligned.m16n8k16.row.col.f32.bf16.bf16.f32 " \
        "{%0,%1,%2,%3}, {%4,%5,%6,%7}, {%8,%9}, {%0,%1,%2,%3};" \
        : "+f"((dd)[0]), "+f"((dd)[1]), "+f"((dd)[2]), "+f"((dd)[3]) \
        : "r"((A)[0]), "r"((A)[1]), "r"((A)[2]), "r"((A)[3]), "r"(b0), "r"(b1))

// smem geometry: 144B row stride (64 bf16 + 8 pad) -> conflict-free ldmatrix
#define ROWB   144
#define HALF_B (128 * ROWB)          // 18432 bytes per (hi|lo) half-tile
#define SB_OFF HALF_B * 2            // A occupies [0, 36864)
#define SMEM_BYTES (HALF_B * 2 * 3)  // A + 2 B buffers = 110592

// ---------------------------------------------------------------------------
// f = x@Wf, g = x@Wg, emitted as bf16 hi/lo split.
// ---------------------------------------------------------------------------
__global__ void __launch_bounds__(256) fg_kernel(const float* __restrict__ x,
                                                 const float* __restrict__ Wf,
                                                 const float* __restrict__ Wg) {
    __shared__ float xs[C_][32];
    __shared__ float ws[2][16][D_];

    const int b    = blockIdx.y;
    const int row0 = blockIdx.x * 32;
    const int r    = threadIdx.x >> 3;
    const int dg   = threadIdx.x & 7;

    {
        const float4* src = reinterpret_cast<const float4*>(
            x + ((size_t)b * N_ + row0 + r) * C_ + dg * 32);
#pragma unroll
        for (int i = 0; i < 8; i++) {
            float4 v = src[i];
            int c = dg * 32 + i * 4;
            xs[c + 0][r] = v.x; xs[c + 1][r] = v.y;
            xs[c + 2][r] = v.z; xs[c + 3][r] = v.w;
        }
    }

    float accf[8] = {}, accg[8] = {};
    for (int c0 = 0; c0 < C_; c0 += 16) {
        __syncthreads();
        {
            const float4* wf4 = reinterpret_cast<const float4*>(Wf + c0 * D_);
            const float4* wg4 = reinterpret_cast<const float4*>(Wg + c0 * D_);
            reinterpret_cast<float4*>(&ws[0][0][0])[threadIdx.x] = wf4[threadIdx.x];
            reinterpret_cast<float4*>(&ws[1][0][0])[threadIdx.x] = wg4[threadIdx.x];
        }
        __syncthreads();
#pragma unroll
        for (int cc = 0; cc < 16; cc++) {
            float xv = xs[c0 + cc][r];
#pragma unroll
            for (int j = 0; j < 8; j++) {
                accf[j] = fmaf(xv, ws[0][cc][dg * 8 + j], accf[j]);
                accg[j] = fmaf(xv, ws[1][cc][dg * 8 + j], accg[j]);
            }
        }
    }

    uint4 fh, fl, gh, gl;
    uint16_t* fhp = (uint16_t*)&fh; uint16_t* flp = (uint16_t*)&fl;
    uint16_t* ghp = (uint16_t*)&gh; uint16_t* glp = (uint16_t*)&gl;
#pragma unroll
    for (int j = 0; j < 8; j++) {
        __nv_bfloat16 h1 = __float2bfloat16_rn(accf[j]);
        __nv_bfloat16 l1 = __float2bfloat16_rn(accf[j] - __bfloat162float(h1));
        __nv_bfloat16 h2 = __float2bfloat16_rn(accg[j]);
        __nv_bfloat16 l2 = __float2bfloat16_rn(accg[j] - __bfloat162float(h2));
        fhp[j] = *(uint16_t*)&h1; flp[j] = *(uint16_t*)&l1;
        ghp[j] = *(uint16_t*)&h2; glp[j] = *(uint16_t*)&l2;
    }
    size_t off = ((size_t)b * N_ + row0 + r) * D_ + dg * 8;
    *reinterpret_cast<uint4*>(g_fhi + off) = fh;
    *reinterpret_cast<uint4*>(g_flo + off) = fl;
    *reinterpret_cast<uint4*>(g_ghi + off) = gh;
    *reinterpret_cast<uint4*>(g_glo + off) = gl;
}

// ---------------------------------------------------------------------------
// Fused two-sweep attention. CTA = 128-row strip of one batch (grid 128).
// Sweep 1: GEMM+exp -> rowsums (regs -> smem). Sweep 2: recompute, scale
// by 1/rowsum, single write of beta. B tiles cp.async double-buffered.
// ---------------------------------------------------------------------------
__device__ __forceinline__ void load_b_tile(uint32_t dst, int b, int col0, int tid) {
#pragma unroll 2
    for (int i = tid; i < 2048; i += 256) {
        int half = i >> 10, j = i & 1023, r = j >> 3, c = j & 7;
        const uint16_t* src = (half ? g_flo : g_fhi) + ((size_t)b * N_ + col0 + r) * D_ + c * 8;
        cp16(dst + half * HALF_B + r * ROWB + c * 16, src);
    }
    CP_COMMIT();
}

__device__ __forceinline__ void compute_tile(uint32_t sA, uint32_t sB,
                                             uint32_t aRow, uint32_t aK8,
                                             uint32_t bRow, uint32_t bK8,
                                             float d[2][8][4]) {
#pragma unroll
    for (int k0 = 0; k0 < 64; k0 += 16) {
        uint32_t ah[2][4], al[2][4];
#pragma unroll
        for (int mi = 0; mi < 2; mi++) {
            uint32_t addr = sA + (aRow + mi * 16) * ROWB + (k0 + aK8) * 2;
            LDSM4(ah[mi], addr);
            LDSM4(al[mi], addr + HALF_B);
        }
#pragma unroll
        for (int p = 0; p < 4; p++) {
            uint32_t bh[4], bl[4];
            uint32_t addr = sB + (bRow + p * 16) * ROWB + (k0 + bK8) * 2;
            LDSM4(bh, addr);
            LDSM4(bl, addr + HALF_B);
#pragma unroll
            for (int mi = 0; mi < 2; mi++) {
                MMA(d[mi][2 * p],     ah[mi], bh[0], bh[2]);
                MMA(d[mi][2 * p + 1], ah[mi], bh[1], bh[3]);
                MMA(d[mi][2 * p],     ah[mi], bl[0], bl[2]);
                MMA(d[mi][2 * p + 1], ah[mi], bl[1], bl[3]);
                MMA(d[mi][2 * p],     al[mi], bh[0], bh[2]);
                MMA(d[mi][2 * p + 1], al[mi], bh[1], bh[3]);
            }
        }
    }
}

__global__ void __launch_bounds__(256, 1) attn_fused_kernel(float* __restrict__ beta) {
    extern __shared__ __align__(16) char smem[];
    __shared__ float srow[128];
    __shared__ float sinv[128];

    const uint32_t sb = smem_u32(smem);
    const int tid  = threadIdx.x;
    const int wid  = tid >> 5;
    const int lane = tid & 31;
    const int b    = blockIdx.x >> 5;
    const int row0 = (blockIdx.x & 31) * 128;

    // A tile (g hi/lo) -> smem, once
#pragma unroll 2
    for (int i = tid; i < 2048; i += 256) {
        int half = i >> 10, j = i & 1023, r = j >> 3, c = j & 7;
        const uint16_t* src = (half ? g_glo : g_ghi) + ((size_t)b * N_ + row0 + r) * D_ + c * 8;
        cp16(sb + half * HALF_B + r * ROWB + c * 16, src);
    }
    if (tid < 128) srow[tid] = 0.0f;
    load_b_tile(sb + SB_OFF, b, 0, tid);   // commits A + B0 together
    CP_WAIT0();
    __syncthreads();

    const int wm = wid & 3, wn = wid >> 2;
    const uint32_t aRow = wm * 32 + (lane & 15);
    const uint32_t aK8  = (lane >> 4) * 8;
    const uint32_t bRow = wn * 64 + ((lane >> 3) & 1) * 8 + (lane & 7);
    const uint32_t bK8  = (lane >> 4) * 8;
    const int gRow  = lane >> 2;
    const int cPair = (lane & 3) * 2;

    float rsum[4] = {0.0f, 0.0f, 0.0f, 0.0f};

    // ---- sweep 1: rowsums ----
    for (int t = 0; t < 32; t++) {
        const uint32_t sB = sb + SB_OFF + (t & 1) * (HALF_B * 2);
        load_b_tile(sb + SB_OFF + ((t + 1) & 1) * (HALF_B * 2), b, ((t + 1) & 31) * 128, tid);

        float d[2][8][4] = {};
        compute_tile(sb, sB, aRow, aK8, bRow, bK8, d);

#pragma unroll
        for (int mi = 0; mi < 2; mi++) {
            float s0 = 0.0f, s1 = 0.0f;
#pragma unroll
            for (int ni = 0; ni < 8; ni++) {
                s0 += __expf(d[mi][ni][0]) + __expf(d[mi][ni][1]);
                s1 += __expf(d[mi][ni][2]) + __expf(d[mi][ni][3]);
            }
            rsum[mi * 2] += s0;
            rsum[mi * 2 + 1] += s1;
        }
        CP_WAIT0();
        __syncthreads();
    }

    // ---- reduce rowsums -> sinv ----
#pragma unroll
    for (int mi = 0; mi < 2; mi++) {
        float s0 = rsum[mi * 2], s1 = rsum[mi * 2 + 1];
        s0 += __shfl_xor_sync(0xffffffffu, s0, 1);
        s0 += __shfl_xor_sync(0xffffffffu, s0, 2);
        s1 += __shfl_xor_sync(0xffffffffu, s1, 1);
        s1 += __shfl_xor_sync(0xffffffffu, s1, 2);
        if ((lane & 3) == 0) {
            int rl0 = wm * 32 + mi * 16 + gRow;
            atomicAdd(&srow[rl0], s0);
            atomicAdd(&srow[rl0 + 8], s1);
        }
    }
    __syncthreads();
    if (tid < 128) sinv[tid] = 1.0f / srow[tid];
    __syncthreads();

    // ---- sweep 2: recompute, normalize, write ----
    for (int t = 32; t < 64; t++) {
        const uint32_t sB = sb + SB_OFF + (t & 1) * (HALF_B * 2);
        if (t < 63)
            load_b_tile(sb + SB_OFF + ((t + 1) & 1) * (HALF_B * 2), b, ((t + 1) & 31) * 128, tid);

        float d[2][8][4] = {};
        compute_tile(sb, sB, aRow, aK8, bRow, bK8, d);

        const int col0 = (t & 31) * 128;
#pragma unroll
        for (int mi = 0; mi < 2; mi++) {
            const int rl0 = wm * 32 + mi * 16 + gRow;
            const float inv0 = sinv[rl0];
            const float inv1 = sinv[rl0 + 8];
            const size_t r0 = (size_t)b * N_ + row0 + rl0;
            const size_t r1 = r0 + 8;
#pragma unroll
            for (int ni = 0; ni < 8; ni++) {
                const int col = col0 + wn * 64 + ni * 8 + cPair;
                *reinterpret_cast<float2*>(beta + r0 * (size_t)N_ + col) =
                    make_float2(__expf(d[mi][ni][0]) * inv0, __expf(d[mi][ni][1]) * inv0);
                *reinterpret_cast<float2*>(beta + r1 * (size_t)N_ + col) =
                    make_float2(__expf(d[mi][ni][2]) * inv1, __expf(d[mi][ni][3]) * inv1);
            }
        }
        CP_WAIT0();
        __syncthreads();
    }
}

// ---------------------------------------------------------------------------
// Generic path (gamma != 0): h = x @ Wh.  Early-exits when gamma == 0.
// ---------------------------------------------------------------------------
__global__ void h_kernel(const float* __restrict__ x, const float* __restrict__ Wh,
                         const float* __restrict__ gamma) {
    if (gamma[0] == 0.0f) return;
    const int b = blockIdx.y;
    for (int nn = 0; nn < 16; nn++) {
        const int n = blockIdx.x * 16 + nn;
        const int c = threadIdx.x;
        const float* xr = x + ((size_t)b * N_ + n) * C_;
        float acc = 0.0f;
        for (int k = 0; k < C_; k++) acc = fmaf(xr[k], Wh[k * C_ + c], acc);
        g_h[((size_t)b * N_ + n) * C_ + c] = acc;
    }
}

// ---------------------------------------------------------------------------
// out = gamma * (beta @ h) + x  (pure vectorized copy when gamma == 0)
// ---------------------------------------------------------------------------
__global__ void __launch_bounds__(256) out_kernel(const float* __restrict__ x,
                                                  const float* __restrict__ gamma,
                                                  float* __restrict__ out,
                                                  const float* __restrict__ beta) {
    const float gm = gamma[0];
    const int i = blockIdx.x * 256 + threadIdx.x;      // float4 index
    if (gm == 0.0f) {
        reinterpret_cast<float4*>(out)[i] = reinterpret_cast<const float4*>(x)[i];
        return;
    }
    const int rowg = i >> 6;                 // global row (b*N + n)
    const int c0   = (i & 63) * 4;
    const float* brow = beta + (size_t)rowg * (size_t)N_;
    const int b = rowg >> 12;
    float acc[4] = {};
    for (int m = 0; m < N_; m++) {
        const float bv = brow[m];
        const float* hr = g_h + ((size_t)b * N_ + m) * C_ + c0;
#pragma unroll
        for (int q = 0; q < 4; q++) acc[q] = fmaf(bv, hr[q], acc[q]);
    }
    const size_t idx = (size_t)rowg * C_ + c0;
#pragma unroll
    for (int q = 0; q < 4; q++) out[idx + q] = fmaf(gm, acc[q], x[idx + q]);
}

// ---------------------------------------------------------------------------
extern "C" void kernel_launch(void* const* d_in, const int* in_sizes, int n_in,
                              void* d_out, int out_size) {
    const float* x     = (const float*)d_in[0];
    const float* Wf    = (const float*)d_in[1];
    const float* Wg    = (const float*)d_in[2];
    const float* Wh    = (const float*)d_in[3];
    const float* gamma = (const float*)d_in[4];

    float* out  = (float*)d_out;
    float* beta = out + (size_t)B_ * N_ * C_;

    cudaFuncSetAttribute(attn_fused_kernel, cudaFuncAttributeMaxDynamicSharedMemorySize,
                         SMEM_BYTES);

    fg_kernel<<<dim3(N_ / 32, B_), 256>>>(x, Wf, Wg);
    h_kernel<<<dim3(N_ / 16, B_), 256>>>(x, Wh, gamma);
    attn_fused_kernel<<<128, 256, SMEM_BYTES>>>(beta);
    out_kernel<<<(B_ * N_ * C_ / 4) / 256, 256>>>(x, gamma, out, beta);
}

// round 5
// speedup vs baseline: 1.3176x; 1.0007x over previous
#include <cuda_runtime.h>
#include <cuda_bf16.h>
#include <stdint.h>
#include <math.h>

#define B_ 4
#define N_ 4096
#define C_ 256
#define D_ 64

// ---- scratch (allocation-free contract) -----------------------------------
__device__ uint16_t g_ghi[B_ * N_ * D_];
__device__ uint16_t g_glo[B_ * N_ * D_];
__device__ uint16_t g_fhi[B_ * N_ * D_];
__device__ uint16_t g_flo[B_ * N_ * D_];
__device__ float    g_h[B_ * N_ * C_];     // only touched if gamma != 0

__device__ __forceinline__ uint32_t smem_u32(const void* p) {
    uint32_t a;
    asm("{ .reg .u64 t; cvta.to.shared.u64 t, %1; cvt.u32.u64 %0, t; }" : "=r"(a) : "l"(p));
    return a;
}
__device__ __forceinline__ void cp16(uint32_t dst, const void* src) {
    asm volatile("cp.async.cg.shared.global [%0], [%1], 16;" :: "r"(dst), "l"(src));
}
#define CP_COMMIT() asm volatile("cp.async.commit_group;" ::: "memory")
#define CP_WAIT0()  asm volatile("cp.async.wait_group 0;" ::: "memory")

#define LDSM4(r, addr) \
    asm volatile("ldmatrix.sync.aligned.m8n8.x4.shared.b16 {%0,%1,%2,%3}, [%4];" \
        : "=r"((r)[0]), "=r"((r)[1]), "=r"((r)[2]), "=r"((r)[3]) : "r"(addr))

#define MMA(dd, A, b0, b1) \
    asm volatile("mma.sync.aligned.m16n8k16.row.col.f32.bf16.bf16.f32 " \
        "{%0,%1,%2,%3}, {%4,%5,%6,%7}, {%8,%9}, {%0,%1,%2,%3};" \
        : "+f"((dd)[0]), "+f"((dd)[1]), "+f"((dd)[2]), "+f"((dd)[3]) \
        : "r"((A)[0]), "r"((A)[1]), "r"((A)[2]), "r"((A)[3]), "r"(b0), "r"(b1))

// smem geometry: 144B row stride (64 bf16 + 8 pad) -> conflict-free ldmatrix
#define ROWB     144
#define A_HALF   (64 * ROWB)              // 9216 B  (A: 64 rows, hi|lo)
#define B_HALF   (128 * ROWB)             // 18432 B (B: 128 rows, hi|lo)
#define A_BYTES  (A_HALF * 2)             // 18432
#define B_BYTES  (B_HALF * 2)             // 36864
#define SB_OFF   A_BYTES                  // B buffers follow A
#define SMEM_BYTES (A_BYTES + 2 * B_BYTES) // 92160

// ---------------------------------------------------------------------------
// f = x@Wf, g = x@Wg, emitted as bf16 hi/lo split.
// ---------------------------------------------------------------------------
__global__ void __launch_bounds__(256) fg_kernel(const float* __restrict__ x,
                                                 const float* __restrict__ Wf,
                                                 const float* __restrict__ Wg) {
    __shared__ float xs[C_][32];
    __shared__ float ws[2][16][D_];

    const int b    = blockIdx.y;
    const int row0 = blockIdx.x * 32;
    const int r    = threadIdx.x >> 3;
    const int dg   = threadIdx.x & 7;

    {
        const float4* src = reinterpret_cast<const float4*>(
            x + ((size_t)b * N_ + row0 + r) * C_ + dg * 32);
#pragma unroll
        for (int i = 0; i < 8; i++) {
            float4 v = src[i];
            int c = dg * 32 + i * 4;
            xs[c + 0][r] = v.x; xs[c + 1][r] = v.y;
            xs[c + 2][r] = v.z; xs[c + 3][r] = v.w;
        }
    }

    float accf[8] = {}, accg[8] = {};
    for (int c0 = 0; c0 < C_; c0 += 16) {
        __syncthreads();
        {
            const float4* wf4 = reinterpret_cast<const float4*>(Wf + c0 * D_);
            const float4* wg4 = reinterpret_cast<const float4*>(Wg + c0 * D_);
            reinterpret_cast<float4*>(&ws[0][0][0])[threadIdx.x] = wf4[threadIdx.x];
            reinterpret_cast<float4*>(&ws[1][0][0])[threadIdx.x] = wg4[threadIdx.x];
        }
        __syncthreads();
#pragma unroll
        for (int cc = 0; cc < 16; cc++) {
            float xv = xs[c0 + cc][r];
#pragma unroll
            for (int j = 0; j < 8; j++) {
                accf[j] = fmaf(xv, ws[0][cc][dg * 8 + j], accf[j]);
                accg[j] = fmaf(xv, ws[1][cc][dg * 8 + j], accg[j]);
            }
        }
    }

    uint4 fh, fl, gh, gl;
    uint16_t* fhp = (uint16_t*)&fh; uint16_t* flp = (uint16_t*)&fl;
    uint16_t* ghp = (uint16_t*)&gh; uint16_t* glp = (uint16_t*)&gl;
#pragma unroll
    for (int j = 0; j < 8; j++) {
        __nv_bfloat16 h1 = __float2bfloat16_rn(accf[j]);
        __nv_bfloat16 l1 = __float2bfloat16_rn(accf[j] - __bfloat162float(h1));
        __nv_bfloat16 h2 = __float2bfloat16_rn(accg[j]);
        __nv_bfloat16 l2 = __float2bfloat16_rn(accg[j] - __bfloat162float(h2));
        fhp[j] = *(uint16_t*)&h1; flp[j] = *(uint16_t*)&l1;
        ghp[j] = *(uint16_t*)&h2; glp[j] = *(uint16_t*)&l2;
    }
    size_t off = ((size_t)b * N_ + row0 + r) * D_ + dg * 8;
    *reinterpret_cast<uint4*>(g_fhi + off) = fh;
    *reinterpret_cast<uint4*>(g_flo + off) = fl;
    *reinterpret_cast<uint4*>(g_ghi + off) = gh;
    *reinterpret_cast<uint4*>(g_glo + off) = gl;
}

// ---------------------------------------------------------------------------
// Fused two-sweep attention. CTA = 64-row strip (grid 256, 2 CTAs/SM).
// Sweep 1: GEMM+exp -> rowsums. Sweep 2: recompute, normalize, write beta.
// ---------------------------------------------------------------------------
__device__ __forceinline__ void load_b_tile(uint32_t dst, int b, int col0, int tid) {
#pragma unroll 2
    for (int i = tid; i < 2048; i += 256) {
        int half = i >> 10, j = i & 1023, r = j >> 3, c = j & 7;
        const uint16_t* src = (half ? g_flo : g_fhi) + ((size_t)b * N_ + col0 + r) * D_ + c * 8;
        cp16(dst + half * B_HALF + r * ROWB + c * 16, src);
    }
    CP_COMMIT();
}

__device__ __forceinline__ void compute_tile(uint32_t sA, uint32_t sB,
                                             uint32_t aRow, uint32_t aK8,
                                             uint32_t bRow, uint32_t bK8,
                                             float d[2][4][4]) {
#pragma unroll
    for (int k0 = 0; k0 < 64; k0 += 16) {
        uint32_t ah[2][4], al[2][4];
#pragma unroll
        for (int mi = 0; mi < 2; mi++) {
            uint32_t addr = sA + (aRow + mi * 16) * ROWB + (k0 + aK8) * 2;
            LDSM4(ah[mi], addr);
            LDSM4(al[mi], addr + A_HALF);
        }
#pragma unroll
        for (int p = 0; p < 2; p++) {
            uint32_t bh[4], bl[4];
            uint32_t addr = sB + (bRow + p * 16) * ROWB + (k0 + bK8) * 2;
            LDSM4(bh, addr);
            LDSM4(bl, addr + B_HALF);
            // term-major: 4 independent accumulators between reuses
#pragma unroll
            for (int mi = 0; mi < 2; mi++) {
                MMA(d[mi][2 * p],     ah[mi], bh[0], bh[2]);
                MMA(d[mi][2 * p + 1], ah[mi], bh[1], bh[3]);
            }
#pragma unroll
            for (int mi = 0; mi < 2; mi++) {
                MMA(d[mi][2 * p],     ah[mi], bl[0], bl[2]);
                MMA(d[mi][2 * p + 1], ah[mi], bl[1], bl[3]);
            }
#pragma unroll
            for (int mi = 0; mi < 2; mi++) {
                MMA(d[mi][2 * p],     al[mi], bh[0], bh[2]);
                MMA(d[mi][2 * p + 1], al[mi], bh[1], bh[3]);
            }
        }
    }
}

__global__ void __launch_bounds__(256, 2) attn_fused_kernel(float* __restrict__ beta) {
    extern __shared__ __align__(16) char smem[];
    __shared__ float srow[64];
    __shared__ float sinv[64];

    const uint32_t sb = smem_u32(smem);
    const int tid  = threadIdx.x;
    const int wid  = tid >> 5;
    const int lane = tid & 31;
    const int b    = blockIdx.x >> 6;
    const int row0 = (blockIdx.x & 63) * 64;

    // A tile (g hi/lo, 64 rows) -> smem, once
    for (int i = tid; i < 1024; i += 256) {
        int half = i >> 9, j = i & 511, r = j >> 3, c = j & 7;
        const uint16_t* src = (half ? g_glo : g_ghi) + ((size_t)b * N_ + row0 + r) * D_ + c * 8;
        cp16(sb + half * A_HALF + r * ROWB + c * 16, src);
    }
    if (tid < 64) srow[tid] = 0.0f;
    load_b_tile(sb + SB_OFF, b, 0, tid);   // commits A + B0 together
    CP_WAIT0();
    __syncthreads();

    const int wm = wid & 1, wn = wid >> 1;              // 2 x 4 warp grid, 32x32 tiles
    const uint32_t aRow = wm * 32 + (lane & 15);
    const uint32_t aK8  = (lane >> 4) * 8;
    const uint32_t bRow = wn * 32 + ((lane >> 3) & 1) * 8 + (lane & 7);
    const uint32_t bK8  = (lane >> 4) * 8;
    const int gRow  = lane >> 2;
    const int cPair = (lane & 3) * 2;

    float rsum[4] = {0.0f, 0.0f, 0.0f, 0.0f};

    // ---- sweep 1: rowsums ----
    for (int t = 0; t < 32; t++) {
        const uint32_t sB = sb + SB_OFF + (t & 1) * B_BYTES;
        load_b_tile(sb + SB_OFF + ((t + 1) & 1) * B_BYTES, b, ((t + 1) & 31) * 128, tid);

        float d[2][4][4] = {};
        compute_tile(sb, sB, aRow, aK8, bRow, bK8, d);

#pragma unroll
        for (int mi = 0; mi < 2; mi++) {
            float s0 = 0.0f, s1 = 0.0f;
#pragma unroll
            for (int ni = 0; ni < 4; ni++) {
                s0 += __expf(d[mi][ni][0]) + __expf(d[mi][ni][1]);
                s1 += __expf(d[mi][ni][2]) + __expf(d[mi][ni][3]);
            }
            rsum[mi * 2] += s0;
            rsum[mi * 2 + 1] += s1;
        }
        CP_WAIT0();
        __syncthreads();
    }

    // ---- reduce rowsums -> sinv ----
#pragma unroll
    for (int mi = 0; mi < 2; mi++) {
        float s0 = rsum[mi * 2], s1 = rsum[mi * 2 + 1];
        s0 += __shfl_xor_sync(0xffffffffu, s0, 1);
        s0 += __shfl_xor_sync(0xffffffffu, s0, 2);
        s1 += __shfl_xor_sync(0xffffffffu, s1, 1);
        s1 += __shfl_xor_sync(0xffffffffu, s1, 2);
        if ((lane & 3) == 0) {
            int rl0 = wm * 32 + mi * 16 + gRow;
            atomicAdd(&srow[rl0], s0);
            atomicAdd(&srow[rl0 + 8], s1);
        }
    }
    __syncthreads();
    if (tid < 64) sinv[tid] = 1.0f / srow[tid];
    __syncthreads();

    // ---- sweep 2: recompute, normalize, write ----
    for (int t = 32; t < 64; t++) {
        const uint32_t sB = sb + SB_OFF + (t & 1) * B_BYTES;
        if (t < 63)
            load_b_tile(sb + SB_OFF + ((t + 1) & 1) * B_BYTES, b, ((t + 1) & 31) * 128, tid);

        float d[2][4][4] = {};
        compute_tile(sb, sB, aRow, aK8, bRow, bK8, d);

        const int col0 = (t & 31) * 128;
#pragma unroll
        for (int mi = 0; mi < 2; mi++) {
            const int rl0 = wm * 32 + mi * 16 + gRow;
            const float inv0 = sinv[rl0];
            const float inv1 = sinv[rl0 + 8];
            const size_t r0 = (size_t)b * N_ + row0 + rl0;
            const size_t r1 = r0 + 8;
#pragma unroll
            for (int ni = 0; ni < 4; ni++) {
                const int col = col0 + wn * 32 + ni * 8 + cPair;
                *reinterpret_cast<float2*>(beta + r0 * (size_t)N_ + col) =
                    make_float2(__expf(d[mi][ni][0]) * inv0, __expf(d[mi][ni][1]) * inv0);
                *reinterpret_cast<float2*>(beta + r1 * (size_t)N_ + col) =
                    make_float2(__expf(d[mi][ni][2]) * inv1, __expf(d[mi][ni][3]) * inv1);
            }
        }
        CP_WAIT0();
        __syncthreads();
    }
}

// ---------------------------------------------------------------------------
// Generic path (gamma != 0): h = x @ Wh.  Early-exits when gamma == 0.
// ---------------------------------------------------------------------------
__global__ void h_kernel(const float* __restrict__ x, const float* __restrict__ Wh,
                         const float* __restrict__ gamma) {
    if (gamma[0] == 0.0f) return;
    const int b = blockIdx.y;
    for (int nn = 0; nn < 16; nn++) {
        const int n = blockIdx.x * 16 + nn;
        const int c = threadIdx.x;
        const float* xr = x + ((size_t)b * N_ + n) * C_;
        float acc = 0.0f;
        for (int k = 0; k < C_; k++) acc = fmaf(xr[k], Wh[k * C_ + c], acc);
        g_h[((size_t)b * N_ + n) * C_ + c] = acc;
    }
}

// ---------------------------------------------------------------------------
// out = gamma * (beta @ h) + x  (pure vectorized copy when gamma == 0)
// ---------------------------------------------------------------------------
__global__ void __launch_bounds__(256) out_kernel(const float* __restrict__ x,
                                                  const float* __restrict__ gamma,
                                                  float* __restrict__ out,
                                                  const float* __restrict__ beta) {
    const float gm = gamma[0];
    const int i = blockIdx.x * 256 + threadIdx.x;      // float4 index
    if (gm == 0.0f) {
        reinterpret_cast<float4*>(out)[i] = reinterpret_cast<const float4*>(x)[i];
        return;
    }
    const int rowg = i >> 6;                 // global row (b*N + n)
    const int c0   = (i & 63) * 4;
    const float* brow = beta + (size_t)rowg * (size_t)N_;
    const int b = rowg >> 12;
    float acc[4] = {};
    for (int m = 0; m < N_; m++) {
        const float bv = brow[m];
        const float* hr = g_h + ((size_t)b * N_ + m) * C_ + c0;
#pragma unroll
        for (int q = 0; q < 4; q++) acc[q] = fmaf(bv, hr[q], acc[q]);
    }
    const size_t idx = (size_t)rowg * C_ + c0;
#pragma unroll
    for (int q = 0; q < 4; q++) out[idx + q] = fmaf(gm, acc[q], x[idx + q]);
}

// ---------------------------------------------------------------------------
extern "C" void kernel_launch(void* const* d_in, const int* in_sizes, int n_in,
                              void* d_out, int out_size) {
    const float* x     = (const float*)d_in[0];
    const float* Wf    = (const float*)d_in[1];
    const float* Wg    = (const float*)d_in[2];
    const float* Wh    = (const float*)d_in[3];
    const float* gamma = (const float*)d_in[4];

    float* out  = (float*)d_out;
    float* beta = out + (size_t)B_ * N_ * C_;

    cudaFuncSetAttribute(attn_fused_kernel, cudaFuncAttributeMaxDynamicSharedMemorySize,
                         SMEM_BYTES);

    fg_kernel<<<dim3(N_ / 32, B_), 256>>>(x, Wf, Wg);
    h_kernel<<<dim3(N_ / 16, B_), 256>>>(x, Wh, gamma);
    attn_fused_kernel<<<256, 256, SMEM_BYTES>>>(beta);
    out_kernel<<<(B_ * N_ * C_ / 4) / 256, 256>>>(x, gamma, out, beta);
}